// round 5
// baseline (speedup 1.0000x reference)
#include <cuda_runtime.h>
#include <cstdint>
#include <cstddef>
#include <cstring>

#define NTIME 20
#define V     128
#define F     128
#define LRELU_ALPHA 0.2f
#define LOG2E 1.4426950408889634f

#define OUT_HP_ELEMS   (NTIME * V * F)
#define ATT_OFF        OUT_HP_ELEMS

__device__ float g_Wh[NTIME * V * F];
__device__ float g_e1[NTIME * V * F];   // scaled by LOG2E
__device__ float g_e2[NTIME * V * F];   // scaled by LOG2E
__device__ float g_C1[F * F];           // W @ a1 * LOG2E
__device__ float g_C2[F * F];           // W @ a2 * LOG2E

// ---- packed f32x2 helpers (Blackwell) --------------------------------------
__device__ __forceinline__ float2 addx2(float2 a, float2 b) {
    unsigned long long ua, ub, uc;
    memcpy(&ua, &a, 8); memcpy(&ub, &b, 8);
    asm("add.rn.f32x2 %0, %1, %2;" : "=l"(uc) : "l"(ua), "l"(ub));
    float2 c; memcpy(&c, &uc, 8); return c;
}
__device__ __forceinline__ float2 mulx2(float2 a, float2 b) {
    unsigned long long ua, ub, uc;
    memcpy(&ua, &a, 8); memcpy(&ub, &b, 8);
    asm("mul.rn.f32x2 %0, %1, %2;" : "=l"(uc) : "l"(ua), "l"(ub));
    float2 c; memcpy(&c, &uc, 8); return c;
}
__device__ __forceinline__ float ex2(float x) {
    float r; asm("ex2.approx.f32 %0, %1;" : "=f"(r) : "f"(x)); return r;
}

// ----------------------------------------------------------------------------
// Kernel 0: C1 = (W @ a1) * LOG2E ; C2 = (W @ a2) * LOG2E
// Block computes 4 rows of C_half; half = tid>>7 picks a1/a2. Grid = 32.
// ----------------------------------------------------------------------------
__global__ void __launch_bounds__(256) prep_C(
    const float* __restrict__ W, const float* __restrict__ a)
{
    __shared__ float ws[4 * F];
    const int tid  = threadIdx.x;
    const int f    = tid & 127;
    const int half = tid >> 7;
    const int m0   = blockIdx.x * 4;

    if (tid < 128)
        ((float4*)ws)[tid] = ((const float4*)(W + (size_t)m0 * F))[tid];
    __syncthreads();

    const float* ap = a + (size_t)half * F * F;
    float acc[4] = {0.f, 0.f, 0.f, 0.f};

#pragma unroll 8
    for (int k4 = 0; k4 < F / 4; k4++) {
        float av[4];
#pragma unroll
        for (int u = 0; u < 4; u++)
            av[u] = __ldg(ap + (k4 * 4 + u) * F + f);
#pragma unroll
        for (int r = 0; r < 4; r++) {
            const float4 wv = ((const float4*)(ws + r * F))[k4];
            acc[r] = fmaf(wv.x, av[0], acc[r]);
            acc[r] = fmaf(wv.y, av[1], acc[r]);
            acc[r] = fmaf(wv.z, av[2], acc[r]);
            acc[r] = fmaf(wv.w, av[3], acc[r]);
        }
    }

    float* dst = half ? g_C2 : g_C1;
#pragma unroll
    for (int r = 0; r < 4; r++)
        dst[(size_t)(m0 + r) * F + f] = acc[r] * LOG2E;
}

// ----------------------------------------------------------------------------
// Kernel 1: {g_Wh, g_e1, g_e2} = h @ {W, C1, C2}
// grid = (160 m-tiles, 3 mats), 256 threads, MT=16, 8 rows/thread.
// ----------------------------------------------------------------------------
#define MT 16

__global__ void __launch_bounds__(256) gemm3(
    const float* __restrict__ h, const float* __restrict__ W)
{
    __shared__ float hs[MT * F];

    const int tid  = threadIdx.x;
    const int f    = tid & 127;
    const int half = tid >> 7;
    const int m0   = blockIdx.x * MT;
    const int by   = blockIdx.y;

    const float* M   = (by == 0) ? W    : ((by == 1) ? g_C1 : g_C2);
    float*       dst = (by == 0) ? g_Wh : ((by == 1) ? g_e1 : g_e2);

    {
        const float4* h4 = (const float4*)(h + (size_t)m0 * F);
        ((float4*)hs)[tid]       = h4[tid];
        ((float4*)hs)[tid + 256] = h4[tid + 256];
    }
    __syncthreads();

    float acc[8] = {0.f,0.f,0.f,0.f,0.f,0.f,0.f,0.f};

#pragma unroll 8
    for (int k4 = 0; k4 < F / 4; k4++) {
        float mv[4];
#pragma unroll
        for (int u = 0; u < 4; u++)
            mv[u] = __ldg(M + (k4 * 4 + u) * F + f);
#pragma unroll
        for (int r = 0; r < 8; r++) {
            const float4 hv = ((const float4*)(hs + (half * 8 + r) * F))[k4];
            acc[r] = fmaf(hv.x, mv[0], acc[r]);
            acc[r] = fmaf(hv.y, mv[1], acc[r]);
            acc[r] = fmaf(hv.z, mv[2], acc[r]);
            acc[r] = fmaf(hv.w, mv[3], acc[r]);
        }
    }

#pragma unroll
    for (int r = 0; r < 8; r++)
        dst[(size_t)(m0 + half * 8 + r) * F + f] = acc[r];
}

// ----------------------------------------------------------------------------
// Kernel 2: fused leakyrelu + mask + softmax + weighted sum + elu + attn write.
// R4 layout (warp = one i, lane = 2 f's, 128-bit reg adjacency mask),
// + fully-unrolled j loops (immediate LDS/STG offsets, no IMAD stream)
// + prescaled-by-log2e e1/e2 and ex2.approx (no mul-by-1.4427)
// + packed f32x2 add/mul for the v / alpha*v computation.
// ----------------------------------------------------------------------------
#define FH  64
#define IPB 16
#define ATTN_SMEM_BYTES ((V * FH * 2) * (int)sizeof(float))

__global__ void __launch_bounds__(512, 3) attn_fused(
    const float* __restrict__ adj,
    float* __restrict__ out)
{
    extern __shared__ float sm[];
    float* e2s = sm;                 // [V][FH]   (scaled by LOG2E)
    float* whs = sm + V * FH;        // [V][FH]

    const int t    = blockIdx.y;
    const int bx   = blockIdx.x;      // 0..15
    const int fh   = bx & 1;
    const int ig   = bx >> 1;         // 0..7
    const int tid  = threadIdx.x;
    const int lane = tid & 31;
    const int il   = tid >> 5;        // warp id = local i
    const int i    = ig * IPB + il;
    const int f2   = fh * FH + lane * 2;

    // adjacency bitmask for row i (warp-uniform registers)
    uint32_t bits[4];
    {
        const float* arow = adj + (size_t)i * V;
#pragma unroll
        for (int w = 0; w < 4; w++)
            bits[w] = __ballot_sync(0xFFFFFFFFu, arow[w * 32 + lane] > 0.0f);
    }

    // cooperative tile loads: each half-tile = 2048 float4
    {
        const float* e2g = g_e2 + (size_t)t * V * F + fh * FH;
        const float* whg = g_Wh + (size_t)t * V * F + fh * FH;
#pragma unroll
        for (int u = 0; u < 4; u++) {
            const int idx = tid + u * 512;
            const int j = idx >> 4, c = idx & 15;
            ((float4*)e2s)[idx] = *(const float4*)(e2g + j * F + c * 4);
            ((float4*)whs)[idx] = *(const float4*)(whg + j * F + c * 4);
        }
    }

    const float2 e1v = *(const float2*)(g_e1 + ((size_t)t * V + i) * F + f2);
    const float2 A2  = make_float2(LRELU_ALPHA, LRELU_ALPHA);
    __syncthreads();

    const float* e2l = e2s + lane * 2;
    const float* whl = whs + lane * 2;

    // Pass A: sum of exp2 + weighted numerator (warp-uniform bit test)
    float s0 = 0.0f, s1 = 0.0f, n0 = 0.0f, n1 = 0.0f;
#pragma unroll
    for (int w = 0; w < 4; w++) {
        const uint32_t bw = bits[w];
        const float* e2w = e2l + w * 32 * FH;
        const float* whw = whl + w * 32 * FH;
#pragma unroll
        for (int b = 0; b < 32; b++) {
            if (bw & (1u << b)) {
                const float2 e2v = *(const float2*)(e2w + b * FH);
                const float2 v   = addx2(e1v, e2v);
                const float2 av  = mulx2(v, A2);
                const float  m0v = fmaxf(v.x, av.x);
                const float  m1v = fmaxf(v.y, av.y);
                const float  p0  = ex2(m0v);
                const float  p1  = ex2(m1v);
                const float2 wv  = *(const float2*)(whw + b * FH);
                s0 += p0;  s1 += p1;
                n0 = fmaf(p0, wv.x, n0);
                n1 = fmaf(p1, wv.y, n1);
            }
        }
    }

    const float r0 = 1.0f / s0;
    const float r1 = 1.0f / s1;

    // h_prime -> elu -> out (first tuple segment)
    {
        const float hp0 = n0 * r0;
        const float hp1 = n1 * r1;
        float2 o;
        o.x = (hp0 > 0.0f) ? hp0 : expm1f(hp0);
        o.y = (hp1 > 0.0f) ? hp1 : expm1f(hp1);
        *(float2*)(out + ((size_t)t * V + i) * F + f2) = o;
    }

    // Pass B: recompute exp2 for unmasked j; stream normalized attention
    float* ab = out + ATT_OFF + (((size_t)t * V + i) * V) * F + f2;
#pragma unroll
    for (int w = 0; w < 4; w++) {
        const uint32_t bw = bits[w];
        const float* e2w = e2l + w * 32 * FH;
        float* abw = ab + (size_t)w * 32 * F;
#pragma unroll
        for (int b = 0; b < 32; b++) {
            float2 pv;
            if (bw & (1u << b)) {
                const float2 e2v = *(const float2*)(e2w + b * FH);
                const float2 v   = addx2(e1v, e2v);
                const float2 av  = mulx2(v, A2);
                const float  m0v = fmaxf(v.x, av.x);
                const float  m1v = fmaxf(v.y, av.y);
                pv.x = ex2(m0v) * r0;
                pv.y = ex2(m1v) * r1;
            } else {
                pv.x = 0.0f; pv.y = 0.0f;
            }
            __stcs((float2*)(abw + b * F), pv);
        }
    }
}

// ----------------------------------------------------------------------------
extern "C" void kernel_launch(void* const* d_in, const int* in_sizes, int n_in,
                              void* d_out, int out_size)
{
    const float* h   = (const float*)d_in[0];   // [2560,128]
    const float* adj = (const float*)d_in[1];   // [128,128,1]
    const float* W   = (const float*)d_in[2];   // [128,128]
    const float* a   = (const float*)d_in[3];   // [256,128]
    float* out = (float*)d_out;

    cudaFuncSetAttribute(attn_fused, cudaFuncAttributeMaxDynamicSharedMemorySize,
                         ATTN_SMEM_BYTES);

    prep_C<<<32, 256>>>(W, a);

    dim3 g1(160, 3);
    gemm3<<<g1, 256>>>(h, W);

    dim3 g2(16, NTIME);
    attn_fused<<<g2, 512, ATTN_SMEM_BYTES>>>(adj, out);
}

// round 6
// speedup vs baseline: 1.0420x; 1.0420x over previous
#include <cuda_runtime.h>
#include <cstdint>
#include <cstddef>
#include <cstring>

#define NTIME 20
#define V     128
#define F     128
#define LRELU_ALPHA 0.2f
#define LOG2E 1.4426950408889634f

#define OUT_HP_ELEMS   (NTIME * V * F)
#define ATT_OFF        OUT_HP_ELEMS

__device__ float g_Wh[NTIME * V * F];
__device__ float g_e1[NTIME * V * F];   // scaled by LOG2E
__device__ float g_e2[NTIME * V * F];   // scaled by LOG2E
__device__ float g_C1[F * F];           // W @ a1 * LOG2E
__device__ float g_C2[F * F];           // W @ a2 * LOG2E

// ---- packed f32x2 helpers (Blackwell) --------------------------------------
__device__ __forceinline__ float2 addx2(float2 a, float2 b) {
    unsigned long long ua, ub, uc;
    memcpy(&ua, &a, 8); memcpy(&ub, &b, 8);
    asm("add.rn.f32x2 %0, %1, %2;" : "=l"(uc) : "l"(ua), "l"(ub));
    float2 c; memcpy(&c, &uc, 8); return c;
}
__device__ __forceinline__ float2 mulx2(float2 a, float2 b) {
    unsigned long long ua, ub, uc;
    memcpy(&ua, &a, 8); memcpy(&ub, &b, 8);
    asm("mul.rn.f32x2 %0, %1, %2;" : "=l"(uc) : "l"(ua), "l"(ub));
    float2 c; memcpy(&c, &uc, 8); return c;
}
__device__ __forceinline__ float ex2(float x) {
    float r; asm("ex2.approx.f32 %0, %1;" : "=f"(r) : "f"(x)); return r;
}

// ----------------------------------------------------------------------------
// Kernel 0 (rewritten, split-K): C{1,2} = (W @ a{1,2}) * LOG2E
// Grid = (128 rows, 2 halves) = 256 blocks. 512 threads: f = tid&127,
// kq = tid>>7 (k-quarter of 32). 32 fully-unrolled LDGs per thread (high MLP),
// then 4-way smem reduction. Latency-hiding via block count, not per-warp ILP.
// ----------------------------------------------------------------------------
__global__ void __launch_bounds__(512) prep_C(
    const float* __restrict__ W, const float* __restrict__ a)
{
    __shared__ float wrow[F];
    __shared__ float red[512];

    const int tid  = threadIdx.x;
    const int f    = tid & 127;
    const int kq   = tid >> 7;          // 0..3
    const int m    = blockIdx.x;        // 0..127
    const int half = blockIdx.y;        // 0..1

    if (tid < 128)
        wrow[tid] = __ldg(W + (size_t)m * F + tid);
    __syncthreads();

    const float* ap = a + (size_t)half * F * F + kq * 32 * F + f;

    float acc = 0.0f;
#pragma unroll
    for (int u = 0; u < 32; u++)
        acc = fmaf(wrow[kq * 32 + u], __ldg(ap + u * F), acc);

    red[tid] = acc;
    __syncthreads();

    if (kq == 0) {
        const float c = (red[f] + red[f + 128]) + (red[f + 256] + red[f + 384]);
        float* dst = half ? g_C2 : g_C1;
        dst[(size_t)m * F + f] = c * LOG2E;
    }
}

// ----------------------------------------------------------------------------
// Kernel 1: {g_Wh, g_e1, g_e2} = h @ {W, C1, C2}
// grid = (160 m-tiles, 3 mats) = 480 blocks, 256 threads, MT=16, 8 rows/thread.
// ----------------------------------------------------------------------------
#define MT 16

__global__ void __launch_bounds__(256) gemm3(
    const float* __restrict__ h, const float* __restrict__ W)
{
    __shared__ float hs[MT * F];

    const int tid  = threadIdx.x;
    const int f    = tid & 127;
    const int half = tid >> 7;
    const int m0   = blockIdx.x * MT;
    const int by   = blockIdx.y;

    const float* M   = (by == 0) ? W    : ((by == 1) ? g_C1 : g_C2);
    float*       dst = (by == 0) ? g_Wh : ((by == 1) ? g_e1 : g_e2);

    {
        const float4* h4 = (const float4*)(h + (size_t)m0 * F);
        ((float4*)hs)[tid]       = h4[tid];
        ((float4*)hs)[tid + 256] = h4[tid + 256];
    }
    __syncthreads();

    float acc[8] = {0.f,0.f,0.f,0.f,0.f,0.f,0.f,0.f};

#pragma unroll 8
    for (int k4 = 0; k4 < F / 4; k4++) {
        float mv[4];
#pragma unroll
        for (int u = 0; u < 4; u++)
            mv[u] = __ldg(M + (k4 * 4 + u) * F + f);
#pragma unroll
        for (int r = 0; r < 8; r++) {
            const float4 hv = ((const float4*)(hs + (half * 8 + r) * F))[k4];
            acc[r] = fmaf(hv.x, mv[0], acc[r]);
            acc[r] = fmaf(hv.y, mv[1], acc[r]);
            acc[r] = fmaf(hv.z, mv[2], acc[r]);
            acc[r] = fmaf(hv.w, mv[3], acc[r]);
        }
    }

#pragma unroll
    for (int r = 0; r < 8; r++)
        dst[(size_t)(m0 + half * 8 + r) * F + f] = acc[r];
}

// ----------------------------------------------------------------------------
// Kernel 2: fused leakyrelu + mask + softmax + weighted sum + elu + attn write.
// Warp = one i (warp-uniform 128-bit adjacency regs), lane = 2 f's in a 64-f
// half; fully-unrolled j loops (immediate LDS/STG offsets); ex2.approx with
// log2e prescaled upstream; packed f32x2 add/mul.
// ----------------------------------------------------------------------------
#define FH  64
#define IPB 16
#define ATTN_SMEM_BYTES ((V * FH * 2) * (int)sizeof(float))

__global__ void __launch_bounds__(512, 3) attn_fused(
    const float* __restrict__ adj,
    float* __restrict__ out)
{
    extern __shared__ float sm[];
    float* e2s = sm;                 // [V][FH]   (scaled by LOG2E)
    float* whs = sm + V * FH;        // [V][FH]

    const int t    = blockIdx.y;
    const int bx   = blockIdx.x;      // 0..15
    const int fh   = bx & 1;
    const int ig   = bx >> 1;         // 0..7
    const int tid  = threadIdx.x;
    const int lane = tid & 31;
    const int il   = tid >> 5;        // warp id = local i
    const int i    = ig * IPB + il;
    const int f2   = fh * FH + lane * 2;

    // adjacency bitmask for row i (warp-uniform registers)
    uint32_t bits[4];
    {
        const float* arow = adj + (size_t)i * V;
#pragma unroll
        for (int w = 0; w < 4; w++)
            bits[w] = __ballot_sync(0xFFFFFFFFu, arow[w * 32 + lane] > 0.0f);
    }

    // cooperative tile loads: each half-tile = 2048 float4
    {
        const float* e2g = g_e2 + (size_t)t * V * F + fh * FH;
        const float* whg = g_Wh + (size_t)t * V * F + fh * FH;
#pragma unroll
        for (int u = 0; u < 4; u++) {
            const int idx = tid + u * 512;
            const int j = idx >> 4, c = idx & 15;
            ((float4*)e2s)[idx] = *(const float4*)(e2g + j * F + c * 4);
            ((float4*)whs)[idx] = *(const float4*)(whg + j * F + c * 4);
        }
    }

    const float2 e1v = *(const float2*)(g_e1 + ((size_t)t * V + i) * F + f2);
    const float2 A2  = make_float2(LRELU_ALPHA, LRELU_ALPHA);
    __syncthreads();

    const float* e2l = e2s + lane * 2;
    const float* whl = whs + lane * 2;

    // Pass A: sum of exp2 + weighted numerator (warp-uniform bit test)
    float s0 = 0.0f, s1 = 0.0f, n0 = 0.0f, n1 = 0.0f;
#pragma unroll
    for (int w = 0; w < 4; w++) {
        const uint32_t bw = bits[w];
        const float* e2w = e2l + w * 32 * FH;
        const float* whw = whl + w * 32 * FH;
#pragma unroll
        for (int b = 0; b < 32; b++) {
            if (bw & (1u << b)) {
                const float2 e2v = *(const float2*)(e2w + b * FH);
                const float2 v   = addx2(e1v, e2v);
                const float2 av  = mulx2(v, A2);
                const float  m0v = fmaxf(v.x, av.x);
                const float  m1v = fmaxf(v.y, av.y);
                const float  p0  = ex2(m0v);
                const float  p1  = ex2(m1v);
                const float2 wv  = *(const float2*)(whw + b * FH);
                s0 += p0;  s1 += p1;
                n0 = fmaf(p0, wv.x, n0);
                n1 = fmaf(p1, wv.y, n1);
            }
        }
    }

    const float r0 = 1.0f / s0;
    const float r1 = 1.0f / s1;

    // h_prime -> elu -> out (first tuple segment)
    {
        const float hp0 = n0 * r0;
        const float hp1 = n1 * r1;
        float2 o;
        o.x = (hp0 > 0.0f) ? hp0 : expm1f(hp0);
        o.y = (hp1 > 0.0f) ? hp1 : expm1f(hp1);
        *(float2*)(out + ((size_t)t * V + i) * F + f2) = o;
    }

    // Pass B: recompute exp2 for unmasked j; stream normalized attention
    float* ab = out + ATT_OFF + (((size_t)t * V + i) * V) * F + f2;
#pragma unroll
    for (int w = 0; w < 4; w++) {
        const uint32_t bw = bits[w];
        const float* e2w = e2l + w * 32 * FH;
        float* abw = ab + (size_t)w * 32 * F;
#pragma unroll
        for (int b = 0; b < 32; b++) {
            float2 pv;
            if (bw & (1u << b)) {
                const float2 e2v = *(const float2*)(e2w + b * FH);
                const float2 v   = addx2(e1v, e2v);
                const float2 av  = mulx2(v, A2);
                const float  m0v = fmaxf(v.x, av.x);
                const float  m1v = fmaxf(v.y, av.y);
                pv.x = ex2(m0v) * r0;
                pv.y = ex2(m1v) * r1;
            } else {
                pv.x = 0.0f; pv.y = 0.0f;
            }
            __stcs((float2*)(abw + b * F), pv);
        }
    }
}

// ----------------------------------------------------------------------------
extern "C" void kernel_launch(void* const* d_in, const int* in_sizes, int n_in,
                              void* d_out, int out_size)
{
    const float* h   = (const float*)d_in[0];   // [2560,128]
    const float* adj = (const float*)d_in[1];   // [128,128,1]
    const float* W   = (const float*)d_in[2];   // [128,128]
    const float* a   = (const float*)d_in[3];   // [256,128]
    float* out = (float*)d_out;

    cudaFuncSetAttribute(attn_fused, cudaFuncAttributeMaxDynamicSharedMemorySize,
                         ATTN_SMEM_BYTES);

    dim3 g0(128, 2);
    prep_C<<<g0, 512>>>(W, a);

    dim3 g1(160, 3);
    gemm3<<<g1, 256>>>(h, W);

    dim3 g2(16, NTIME);
    attn_fused<<<g2, 512, ATTN_SMEM_BYTES>>>(adj, out);
}

// round 7
// speedup vs baseline: 1.1063x; 1.0617x over previous
#include <cuda_runtime.h>
#include <cstdint>
#include <cstddef>
#include <cstring>

#define NTIME 20
#define V     128
#define F     128
#define LRELU_ALPHA 0.2f
#define LOG2E 1.4426950408889634f

#define OUT_HP_ELEMS   (NTIME * V * F)
#define ATT_OFF        OUT_HP_ELEMS

__device__ float g_Wh[NTIME * V * F];
__device__ float g_e1[NTIME * V * F];   // scaled by LOG2E
__device__ float g_e2[NTIME * V * F];   // scaled by LOG2E
__device__ float g_C1[F * F];           // W @ a1 * LOG2E
__device__ float g_C2[F * F];           // W @ a2 * LOG2E

// ---- packed f32x2 helpers (Blackwell) --------------------------------------
__device__ __forceinline__ float2 addx2(float2 a, float2 b) {
    unsigned long long ua, ub, uc;
    memcpy(&ua, &a, 8); memcpy(&ub, &b, 8);
    asm("add.rn.f32x2 %0, %1, %2;" : "=l"(uc) : "l"(ua), "l"(ub));
    float2 c; memcpy(&c, &uc, 8); return c;
}
__device__ __forceinline__ float2 mulx2(float2 a, float2 b) {
    unsigned long long ua, ub, uc;
    memcpy(&ua, &a, 8); memcpy(&ub, &b, 8);
    asm("mul.rn.f32x2 %0, %1, %2;" : "=l"(uc) : "l"(ua), "l"(ub));
    float2 c; memcpy(&c, &uc, 8); return c;
}
__device__ __forceinline__ float ex2(float x) {
    float r; asm("ex2.approx.f32 %0, %1;" : "=f"(r) : "f"(x)); return r;
}

// ----------------------------------------------------------------------------
// Kernel A: blocks [0,160): Wh = h @ W (MT=16, 4 rows/thread)
//           blocks [160,416): split-K C{1,2} = (W @ a{1,2}) * LOG2E
// Single launch so prep_C rides behind the Wh gemm instead of serializing.
// ----------------------------------------------------------------------------
#define MT 16

__global__ void __launch_bounds__(512) gemmA(
    const float* __restrict__ h,
    const float* __restrict__ W,
    const float* __restrict__ a)
{
    __shared__ float smem[MT * F];   // Wh path: h tile; prep path: wrow+red

    const int tid = threadIdx.x;
    const int f   = tid & 127;
    const int q   = tid >> 7;        // 0..3

    if (blockIdx.x < 160) {
        // ---- Wh = h @ W, 16 rows, 4 rows/thread-quarter ----
        const int m0 = blockIdx.x * MT;
        ((float4*)smem)[tid] = ((const float4*)(h + (size_t)m0 * F))[tid];
        __syncthreads();

        float acc[4] = {0.f, 0.f, 0.f, 0.f};
#pragma unroll 8
        for (int k4 = 0; k4 < F / 4; k4++) {
            float mv[4];
#pragma unroll
            for (int u = 0; u < 4; u++)
                mv[u] = __ldg(W + (k4 * 4 + u) * F + f);
#pragma unroll
            for (int r = 0; r < 4; r++) {
                const float4 hv = ((const float4*)(smem + (q * 4 + r) * F))[k4];
                acc[r] = fmaf(hv.x, mv[0], acc[r]);
                acc[r] = fmaf(hv.y, mv[1], acc[r]);
                acc[r] = fmaf(hv.z, mv[2], acc[r]);
                acc[r] = fmaf(hv.w, mv[3], acc[r]);
            }
        }
#pragma unroll
        for (int r = 0; r < 4; r++)
            g_Wh[(size_t)(m0 + q * 4 + r) * F + f] = acc[r];
    } else {
        // ---- split-K C: block handles one (m, half) ----
        float* wrow = smem;          // [128]
        float* red  = smem + 128;    // [512]
        const int idx  = blockIdx.x - 160;
        const int m    = idx & 127;
        const int half = idx >> 7;

        if (tid < 128)
            wrow[tid] = __ldg(W + (size_t)m * F + tid);
        __syncthreads();

        const float* ap = a + (size_t)half * F * F + q * 32 * F + f;
        float acc = 0.0f;
#pragma unroll
        for (int u = 0; u < 32; u++)
            acc = fmaf(wrow[q * 32 + u], __ldg(ap + u * F), acc);

        red[tid] = acc;
        __syncthreads();

        if (q == 0) {
            const float c = (red[f] + red[f + 128]) + (red[f + 256] + red[f + 384]);
            float* dst = half ? g_C2 : g_C1;
            dst[(size_t)m * F + f] = c * LOG2E;
        }
    }
}

// ----------------------------------------------------------------------------
// Kernel B: g_e1 = h @ C1 ; g_e2 = h @ C2   (grid 160 x 2, MT=16)
// ----------------------------------------------------------------------------
__global__ void __launch_bounds__(512) gemmB(const float* __restrict__ h)
{
    __shared__ float hs[MT * F];

    const int tid = threadIdx.x;
    const int f   = tid & 127;
    const int q   = tid >> 7;
    const int m0  = blockIdx.x * MT;
    const int by  = blockIdx.y;

    const float* M   = by ? g_C2 : g_C1;
    float*       dst = by ? g_e2 : g_e1;

    ((float4*)hs)[tid] = ((const float4*)(h + (size_t)m0 * F))[tid];
    __syncthreads();

    float acc[4] = {0.f, 0.f, 0.f, 0.f};
#pragma unroll 8
    for (int k4 = 0; k4 < F / 4; k4++) {
        float mv[4];
#pragma unroll
        for (int u = 0; u < 4; u++)
            mv[u] = __ldg(M + (k4 * 4 + u) * F + f);
#pragma unroll
        for (int r = 0; r < 4; r++) {
            const float4 hv = ((const float4*)(hs + (q * 4 + r) * F))[k4];
            acc[r] = fmaf(hv.x, mv[0], acc[r]);
            acc[r] = fmaf(hv.y, mv[1], acc[r]);
            acc[r] = fmaf(hv.z, mv[2], acc[r]);
            acc[r] = fmaf(hv.w, mv[3], acc[r]);
        }
    }
#pragma unroll
    for (int r = 0; r < 4; r++)
        dst[(size_t)(m0 + q * 4 + r) * F + f] = acc[r];
}

// ----------------------------------------------------------------------------
// Kernel C: attention. j-SPLIT decomposition: two warps per (i, f-half), each
// owning 64 j's -> 10240 total warps (2x R6) -> occupancy ceiling gone.
// Warp w: il = w>>1 (local i), jh = w&1 (j-half). Pass A partial (s, num)
// exchanged through smem; both warps run Pass B on their own j-half.
// Block = 512 threads (8 i x 2 jh), grid = 32 x 20 = 640, smem 72KB -> 3 CTA/SM.
// ----------------------------------------------------------------------------
#define FH  64
#define IPB 8
#define ATTN_SMEM_BYTES ((2 * V * FH + 16 * 32 * 4) * (int)sizeof(float))

__global__ void __launch_bounds__(512, 3) attn_fused(
    const float* __restrict__ adj,
    float* __restrict__ out)
{
    extern __shared__ float sm[];
    float*  e2s = sm;                       // [V][FH]  (scaled by LOG2E)
    float*  whs = sm + V * FH;              // [V][FH]
    float4* red = (float4*)(sm + 2 * V * FH); // [16 warps][32 lanes]

    const int t    = blockIdx.y;
    const int bx   = blockIdx.x;      // 0..31
    const int fh   = bx & 1;
    const int ig   = bx >> 1;         // 0..15
    const int tid  = threadIdx.x;
    const int lane = tid & 31;
    const int w    = tid >> 5;        // warp 0..15
    const int il   = w >> 1;          // local i 0..7
    const int jh   = w & 1;           // j-half
    const int i    = ig * IPB + il;
    const int f2   = fh * FH + lane * 2;

    // adjacency bits for this warp's 64 j's (warp-uniform registers)
    uint32_t bits[2];
    {
        const float* arow = adj + (size_t)i * V + jh * 64;
        bits[0] = __ballot_sync(0xFFFFFFFFu, arow[lane]      > 0.0f);
        bits[1] = __ballot_sync(0xFFFFFFFFu, arow[32 + lane] > 0.0f);
    }

    // cooperative tile loads: each tile = 2048 float4, 4 per thread
    {
        const float* e2g = g_e2 + (size_t)t * V * F + fh * FH;
        const float* whg = g_Wh + (size_t)t * V * F + fh * FH;
#pragma unroll
        for (int u = 0; u < 4; u++) {
            const int idx = tid + u * 512;
            const int j = idx >> 4, c = idx & 15;
            ((float4*)e2s)[idx] = *(const float4*)(e2g + j * F + c * 4);
            ((float4*)whs)[idx] = *(const float4*)(whg + j * F + c * 4);
        }
    }

    const float2 e1v = *(const float2*)(g_e1 + ((size_t)t * V + i) * F + f2);
    const float2 A2  = make_float2(LRELU_ALPHA, LRELU_ALPHA);
    __syncthreads();

    const float* e2l = e2s + jh * 64 * FH + lane * 2;
    const float* whl = whs + jh * 64 * FH + lane * 2;

    // Pass A over this warp's 64 j's: partial sum of exp2 + weighted numerator
    float s0 = 0.0f, s1 = 0.0f, n0 = 0.0f, n1 = 0.0f;
#pragma unroll
    for (int ww = 0; ww < 2; ww++) {
        const uint32_t bw = bits[ww];
        const float* e2w = e2l + ww * 32 * FH;
        const float* whw = whl + ww * 32 * FH;
#pragma unroll
        for (int b = 0; b < 32; b++) {
            if (bw & (1u << b)) {
                const float2 e2v = *(const float2*)(e2w + b * FH);
                const float2 v   = addx2(e1v, e2v);
                const float2 av  = mulx2(v, A2);
                const float  m0v = fmaxf(v.x, av.x);
                const float  m1v = fmaxf(v.y, av.y);
                const float  p0  = ex2(m0v);
                const float  p1  = ex2(m1v);
                const float2 wv  = *(const float2*)(whw + b * FH);
                s0 += p0;  s1 += p1;
                n0 = fmaf(p0, wv.x, n0);
                n1 = fmaf(p1, wv.y, n1);
            }
        }
    }

    // exchange partials with partner warp (w ^ 1)
    red[w * 32 + lane] = make_float4(s0, s1, n0, n1);
    __syncthreads();
    {
        const float4 o = red[(w ^ 1) * 32 + lane];
        s0 += o.x; s1 += o.y; n0 += o.z; n1 += o.w;
    }

    const float r0 = 1.0f / s0;
    const float r1 = 1.0f / s1;

    // h_prime -> elu -> out (one warp of the pair writes)
    if (jh == 0) {
        const float hp0 = n0 * r0;
        const float hp1 = n1 * r1;
        float2 o;
        o.x = (hp0 > 0.0f) ? hp0 : expm1f(hp0);
        o.y = (hp1 > 0.0f) ? hp1 : expm1f(hp1);
        *(float2*)(out + ((size_t)t * V + i) * F + f2) = o;
    }

    // Pass B over own 64 j's: recompute exp2, normalize, stream out
    float* ab = out + ATT_OFF + (((size_t)t * V + i) * V + jh * 64) * F + f2;
#pragma unroll
    for (int ww = 0; ww < 2; ww++) {
        const uint32_t bw = bits[ww];
        const float* e2w = e2l + ww * 32 * FH;
        float* abw = ab + (size_t)ww * 32 * F;
#pragma unroll
        for (int b = 0; b < 32; b++) {
            float2 pv;
            if (bw & (1u << b)) {
                const float2 e2v = *(const float2*)(e2w + b * FH);
                const float2 v   = addx2(e1v, e2v);
                const float2 av  = mulx2(v, A2);
                const float  m0v = fmaxf(v.x, av.x);
                const float  m1v = fmaxf(v.y, av.y);
                pv.x = ex2(m0v) * r0;
                pv.y = ex2(m1v) * r1;
            } else {
                pv.x = 0.0f; pv.y = 0.0f;
            }
            __stcs((float2*)(abw + b * F), pv);
        }
    }
}

// ----------------------------------------------------------------------------
extern "C" void kernel_launch(void* const* d_in, const int* in_sizes, int n_in,
                              void* d_out, int out_size)
{
    const float* h   = (const float*)d_in[0];   // [2560,128]
    const float* adj = (const float*)d_in[1];   // [128,128,1]
    const float* W   = (const float*)d_in[2];   // [128,128]
    const float* a   = (const float*)d_in[3];   // [256,128]
    float* out = (float*)d_out;

    cudaFuncSetAttribute(attn_fused, cudaFuncAttributeMaxDynamicSharedMemorySize,
                         ATTN_SMEM_BYTES);

    gemmA<<<416, 512>>>(h, W, a);

    dim3 g1(160, 2);
    gemmB<<<g1, 512>>>(h);

    dim3 g2(32, NTIME);
    attn_fused<<<g2, 512, ATTN_SMEM_BYTES>>>(adj, out);
}